// round 4
// baseline (speedup 1.0000x reference)
#include <cuda_runtime.h>

// Problem constants (fixed by setup_inputs)
#define Mdim 32
#define Ndim 4
#define Ldim 2048
#define Hdim 64
#define Kdim 5
#define Gg   10
#define NSTEPS 20

// Tiling
#define LT 128
#define NT 256
#define TILES (Ldim / LT)   // 16

// Channel-pair interleaved smem layout (all indices in floats).
// su2 / sh2 hold float2 pairs {val[2cp], val[2cp+1]} per position.
#define SU_STR 136          // float2 stride per ci-pair row (= LT+8)
#define SH_STR 132          // float2 stride per ci-pair row (= LT+4)

#define SM_W1I 0                        // 64*4*5 interleaved pairs = 2560 floats (red alias)
#define SM_B1  (SM_W1I + 2560)          // 64
#define SM_W2I (SM_B1 + 64)             // 4*64*5 interleaved pairs = 2560
#define SM_B2  (SM_W2I + 2560)          // 4
#define SM_SU  (SM_B2 + 4)              // 2 pairs * SU_STR * 2 = 544
#define SM_SH  (SM_SU + 2 * SU_STR * 2) // 32 pairs * SH_STR * 2 = 8448
#define SM_TOT (SM_SH + 32 * SH_STR * 2) // 14180 floats = 56720 B -> 4 CTAs/SM

// Scratch state buffers (no cudaMalloc allowed)
__device__ float g_bufA[Mdim * Ndim * Ldim];
__device__ float g_bufB[Mdim * Ndim * Ldim];
__device__ float g_bufC0[Mdim * Ndim * Ldim];
__device__ float g_bufC1[Mdim * Ndim * Ldim];

typedef unsigned long long ull;

// Packed fp32x2 FMA (Blackwell native): a = w * x + a on both halves.
__device__ __forceinline__ void ffma2(ull& a, ull w, ull x) {
    asm("fma.rn.f32x2 %0, %1, %2, %0;" : "+l"(a) : "l"(w), "l"(x));
}
__device__ __forceinline__ float2 upk(ull v) {
    float2 f;
    asm("mov.b64 {%0, %1}, %2;" : "=f"(f.x), "=f"(f.y) : "l"(v));
    return f;
}

__device__ __forceinline__ float my_tanh(float x) {
    float e = __expf(2.0f * x);
    return 1.0f - __fdividef(2.0f, e + 1.0f);
}

// One RK stage: out = bdry(alpha*z + beta*u + gamma*conv2(tanh(conv1(u))))
__global__ void __launch_bounds__(NT)
stage_kernel(const float* __restrict__ z, const float* __restrict__ u,
             float* __restrict__ out,
             const float* __restrict__ W1, const float* __restrict__ b1,
             const float* __restrict__ W2, const float* __restrict__ b2,
             float alpha, float beta, float gamma)
{
    extern __shared__ float s[];
    const int tid  = threadIdx.x;
    const int m    = blockIdx.y;
    const int base = blockIdx.x * LT;

    // ---- setup: interleave weights by ci-pairs; load biases ----
    for (int i = tid; i < Hdim * Ndim * Kdim; i += NT) {      // W1[co][ci][k]
        int co = i / (Ndim * Kdim);
        int r  = i - co * (Ndim * Kdim);
        int ci = r / Kdim, k = r - ci * Kdim;
        s[SM_W1I + ((co * 2 + (ci >> 1)) * Kdim + k) * 2 + (ci & 1)] = W1[i];
    }
    for (int i = tid; i < Hdim; i += NT) s[SM_B1 + i] = b1[i];
    for (int i = tid; i < Ndim * Hdim * Kdim; i += NT) {      // W2[co][ci][k]
        int co = i / (Hdim * Kdim);
        int r  = i - co * (Hdim * Kdim);
        int ci = r / Kdim, k = r - ci * Kdim;
        s[SM_W2I + ((co * 32 + (ci >> 1)) * Kdim + k) * 2 + (ci & 1)] = W2[i];
    }
    for (int i = tid; i < Ndim; i += NT) s[SM_B2 + i] = b2[i];

    // ---- load u tile, halo 4, interleaved by ci-pair, zero at edges ----
    for (int t = tid; t < Ndim * (LT + 8); t += NT) {
        int ci = t / (LT + 8);
        int j  = t - ci * (LT + 8);
        int gx = base - 4 + j;
        float v = 0.0f;
        if (gx >= 0 && gx < Ldim) v = u[(m * Ndim + ci) * Ldim + gx];
        s[SM_SU + ((ci >> 1) * SU_STR + j) * 2 + (ci & 1)] = v;
    }
    __syncthreads();

    // ---- Phase A: h1 = tanh(conv1(u)) at positions jh in [0, LT+4) ----
    // (global hx = base-2+jh). thread: co = tid>>2, psub = tid&3, 4 pos/iter.
    {
        const int co   = tid >> 2;
        const int psub = tid & 3;
        const float b1c = s[SM_B1 + co];
        const int cpair = co >> 1;
        const int half  = co & 1;

        for (int pb = psub; pb < (LT + 4) / 4; pb += 4) {
            const int jh0 = pb * 4;
            ull A[4] = {0ull, 0ull, 0ull, 0ull};
#pragma unroll
            for (int cp = 0; cp < 2; cp++) {
                // 8 packed position values: su idx jh0..jh0+7
                const float4* xp = (const float4*)&s[SM_SU + (cp * SU_STR + jh0) * 2];
                float4 v0 = xp[0], v1 = xp[1], v2 = xp[2], v3 = xp[3];
                ull X[8];
                X[0] = *(ull*)&v0.x; X[1] = *(ull*)&v0.z;
                X[2] = *(ull*)&v1.x; X[3] = *(ull*)&v1.z;
                X[4] = *(ull*)&v2.x; X[5] = *(ull*)&v2.z;
                X[6] = *(ull*)&v3.x; X[7] = *(ull*)&v3.z;
                const ull* wp = (const ull*)&s[SM_W1I + ((co * 2 + cp) * Kdim) * 2];
                ull W[Kdim];
#pragma unroll
                for (int k = 0; k < Kdim; k++) W[k] = wp[k];
#pragma unroll
                for (int j = 0; j < 4; j++)
#pragma unroll
                    for (int k = 0; k < Kdim; k++)
                        ffma2(A[j], W[k], X[j + k]);
            }
#pragma unroll
            for (int j = 0; j < 4; j++) {
                int hx = base - 2 + jh0 + j;
                float2 f = upk(A[j]);
                float v = (hx >= 0 && hx < Ldim) ? my_tanh(f.x + f.y + b1c) : 0.0f;
                s[SM_SH + (cpair * SH_STR + jh0 + j) * 2 + half] = v;
            }
        }
    }
    __syncthreads();

    // ---- Phase B: conv2 over h1 (32 ci-pairs split across 2 thread halves) ----
    // thread: co = tid&3, pg = (tid>>2)&31 -> positions [4pg, 4pg+4), half = tid>>7
    {
        const int co   = tid & 3;
        const int pg   = (tid >> 2) & 31;
        const int half = tid >> 7;
        const int p0   = pg * 4;

        ull A[4] = {0ull, 0ull, 0ull, 0ull};
        const int cp0 = half * 16;
#pragma unroll 4
        for (int cc = 0; cc < 16; cc++) {
            const int cp = cp0 + cc;
            // conv2 output p0+j uses h1 at jh = p0+j+k (sh row offset == out pos)
            const float4* xp = (const float4*)&s[SM_SH + (cp * SH_STR + p0) * 2];
            float4 v0 = xp[0], v1 = xp[1], v2 = xp[2], v3 = xp[3];
            ull X[8];
            X[0] = *(ull*)&v0.x; X[1] = *(ull*)&v0.z;
            X[2] = *(ull*)&v1.x; X[3] = *(ull*)&v1.z;
            X[4] = *(ull*)&v2.x; X[5] = *(ull*)&v2.z;
            X[6] = *(ull*)&v3.x; X[7] = *(ull*)&v3.z;
            const ull* wp = (const ull*)&s[SM_W2I + ((co * 32 + cp) * Kdim) * 2];
            ull W[Kdim];
#pragma unroll
            for (int k = 0; k < Kdim; k++) W[k] = wp[k];
#pragma unroll
            for (int j = 0; j < 4; j++)
#pragma unroll
                for (int k = 0; k < Kdim; k++)
                    ffma2(A[j], W[k], X[j + k]);
        }

        // upper half deposits packed partials into the (dead) W1I region
        if (half == 1) {
            ull* rp = (ull*)&s[SM_W1I + ((co * 32 + pg) * 4) * 2];
#pragma unroll
            for (int j = 0; j < 4; j++) rp[j] = A[j];
        }
        __syncthreads();

        if (half == 0) {
            const float b2c = s[SM_B2 + co];
            const ull* rp = (const ull*)&s[SM_W1I + ((co * 32 + pg) * 4) * 2];
            float acc[4];
#pragma unroll
            for (int j = 0; j < 4; j++) {
                float2 a = upk(A[j]);
                float2 r = upk(rp[j]);
                acc[j] = a.x + a.y + r.x + r.y + b2c;
            }

            const int row = (m * Ndim + co) * Ldim;
            float4 zv = *(const float4*)&z[row + base + p0];
            float zz[4] = {zv.x, zv.y, zv.z, zv.w};

#pragma unroll
            for (int j = 0; j < 4; j++) {
                float uu = s[SM_SU + ((co >> 1) * SU_STR + 4 + p0 + j) * 2 + (co & 1)];
                float val = alpha * zz[j] + beta * uu + gamma * acc[j];
                int x = base + p0 + j;
                // fused bdry: periodic ghost refresh, each out element written once
                if (x >= Gg && x < Ldim - Gg)            out[row + x] = val;
                if (x >= Ldim - 2 * Gg && x < Ldim - Gg) out[row + x - (Ldim - 2 * Gg)] = val;
                if (x >= Gg && x < 2 * Gg)               out[row + x + (Ldim - 2 * Gg)] = val;
            }
        }
    }
}

extern "C" void kernel_launch(void* const* d_in, const int* in_sizes, int n_in,
                              void* d_out, int out_size) {
    const float* z0 = (const float*)d_in[0];
    const float* W1 = (const float*)d_in[1];
    const float* b1 = (const float*)d_in[2];
    const float* W2 = (const float*)d_in[3];
    const float* b2 = (const float*)d_in[4];
    float* out = (float*)d_out;

    float *A, *B, *C0, *C1;
    cudaGetSymbolAddress((void**)&A,  g_bufA);
    cudaGetSymbolAddress((void**)&B,  g_bufB);
    cudaGetSymbolAddress((void**)&C0, g_bufC0);
    cudaGetSymbolAddress((void**)&C1, g_bufC1);

    const size_t smem = SM_TOT * sizeof(float);
    cudaFuncSetAttribute(stage_kernel, cudaFuncAttributeMaxDynamicSharedMemorySize,
                         (int)smem);

    dim3 grid(TILES, Mdim);
    dim3 blk(NT);

    const float h = 1.0f / (float)NSTEPS;  // t1_t0 = 1 -> h = 0.05

    const float* Z = z0;
    float* cbuf[2] = {C0, C1};
    for (int st = 0; st < NSTEPS; st++) {
        float* zo = (st == NSTEPS - 1) ? out : cbuf[st & 1];
        // k1 = bdry(z + h f(z))
        stage_kernel<<<grid, blk, smem>>>(Z, Z, A, W1, b1, W2, b2,
                                          1.0f, 0.0f, h);
        // k2 = bdry(0.75 z + 0.25 k1 + 0.25 h f(k1))
        stage_kernel<<<grid, blk, smem>>>(Z, A, B, W1, b1, W2, b2,
                                          0.75f, 0.25f, 0.25f * h);
        // z' = bdry(z/3 + 2/3 k2 + 2h/3 f(k2))
        stage_kernel<<<grid, blk, smem>>>(Z, B, zo, W1, b1, W2, b2,
                                          1.0f / 3.0f, 2.0f / 3.0f, (2.0f / 3.0f) * h);
        Z = zo;
    }
}

// round 6
// speedup vs baseline: 1.1589x; 1.1589x over previous
#include <cuda_runtime.h>

// Problem constants (fixed by setup_inputs)
#define Mdim 32
#define Ndim 4
#define Ldim 2048
#define Hdim 64
#define Kdim 5
#define Gg   10
#define NSTEPS 20

// Tiling
#define LT 128
#define NT 256
#define TILES (Ldim / LT)   // 16

// Shared memory layout (floats)
#define SU_STR (LT + 8)      // 136 u row: halo 4 each side
#define SH_STR (LT + 4)      // 132 h1 row: positions base-2 .. base+LT+1
#define SM_W1  0                             // 64*4*5 = 1280
#define SM_B1  (SM_W1 + Hdim * Ndim * Kdim)  // 1280
#define SM_W2P (SM_B1 + Hdim)                // 1344: W2 k-padded to 8 -> 4*64*8 = 2048
#define SM_B2  (SM_W2P + Ndim * Hdim * 8)    // 3392
#define SM_SU  (SM_B2 + Ndim)                // 3396
#define SM_SH  (SM_SU + Ndim * SU_STR)       // 3940
#define SM_TOT (SM_SH + Hdim * SH_STR)       // 12388 floats = 49552 B -> 4 CTAs/SM

// Scratch state buffers (no cudaMalloc allowed)
__device__ float g_bufA[Mdim * Ndim * Ldim];
__device__ float g_bufB[Mdim * Ndim * Ldim];
__device__ float g_bufC0[Mdim * Ndim * Ldim];
__device__ float g_bufC1[Mdim * Ndim * Ldim];

__device__ __forceinline__ float my_tanh(float x) {
    float e = __expf(2.0f * x);
    return 1.0f - __fdividef(2.0f, e + 1.0f);
}

// One RK stage: out = bdry(alpha*z + beta*u + gamma*conv2(tanh(conv1(u))))
// both convs 'same' zero-padding (pad=2).
__global__ void __launch_bounds__(NT)
stage_kernel(const float* __restrict__ z, const float* __restrict__ u,
             float* __restrict__ out,
             const float* __restrict__ W1, const float* __restrict__ b1,
             const float* __restrict__ W2, const float* __restrict__ b2,
             float alpha, float beta, float gamma)
{
    extern __shared__ float s[];
    const int tid  = threadIdx.x;
    const int m    = blockIdx.y;
    const int base = blockIdx.x * LT;

    // ---- weights into smem (W2 padded: [co][ci][8], k=5..7 zero) ----
    for (int i = tid; i < Hdim * Ndim * Kdim; i += NT) s[SM_W1 + i] = W1[i];
    for (int i = tid; i < Hdim; i += NT)               s[SM_B1 + i] = b1[i];
    for (int i = tid; i < Ndim * Hdim * 8; i += NT) {
        int cc = i >> 3;            // co*64 + ci
        int k  = i & 7;
        s[SM_W2P + i] = (k < Kdim) ? W2[cc * Kdim + k] : 0.0f;
    }
    for (int i = tid; i < Ndim; i += NT)               s[SM_B2 + i] = b2[i];

    // ---- u tile with halo 4 (zero at domain edges) ----
    for (int t = tid; t < Ndim * SU_STR; t += NT) {
        int ci = t / SU_STR;
        int j  = t - ci * SU_STR;
        int gx = base - 4 + j;
        float v = 0.0f;
        if (gx >= 0 && gx < Ldim) v = u[(m * Ndim + ci) * Ldim + gx];
        s[SM_SU + ci * SU_STR + j] = v;
    }
    __syncthreads();

    // ---- Phase A: h1 = tanh(conv1(u)) at sh index jh in [0, LT+4) ----
    // global hx = base - 2 + jh. thread: co = tid>>2, psub = tid&3, 4 pos/iter.
    {
        const int co   = tid >> 2;
        const int psub = tid & 3;
        float w1r[Ndim][Kdim];
#pragma unroll
        for (int ci = 0; ci < Ndim; ci++)
#pragma unroll
            for (int k = 0; k < Kdim; k++)
                w1r[ci][k] = s[SM_W1 + (co * Ndim + ci) * Kdim + k];
        const float b1c = s[SM_B1 + co];

        // (LT+4)/4 = 33 quads
        for (int pb = psub; pb < (LT + 4) / 4; pb += 4) {
            const int jh0 = pb * 4;   // multiple of 4 -> float4-safe
            float acc[4] = {b1c, b1c, b1c, b1c};
#pragma unroll
            for (int ci = 0; ci < Ndim; ci++) {
                const float* sup = &s[SM_SU + ci * SU_STR + jh0];
                float4 va = *(const float4*)(sup);
                float4 vb = *(const float4*)(sup + 4);
                float x[8] = {va.x, va.y, va.z, va.w, vb.x, vb.y, vb.z, vb.w};
#pragma unroll
                for (int j = 0; j < 4; j++)
#pragma unroll
                    for (int k = 0; k < Kdim; k++)
                        acc[j] = fmaf(w1r[ci][k], x[j + k], acc[j]);
            }
#pragma unroll
            for (int j = 0; j < 4; j++) {
                int hx = base - 2 + jh0 + j;
                float v = (hx >= 0 && hx < Ldim) ? my_tanh(acc[j]) : 0.0f;
                s[SM_SH + co * SH_STR + jh0 + j] = v;
            }
        }
    }
    __syncthreads();

    // ---- Phase B: conv2 over h1; thread: co = tid&3, 2 positions ----
    // out pos p uses sh indices p..p+4. All activation loads are float2
    // (8B-aligned for every even p0) -- no float4 here (p0 may be 2 mod 4).
    {
        const int co = tid & 3;
        const int p0 = (tid >> 2) * 2;       // 0..126, even

        const float b2c = s[SM_B2 + co];
        float acc0 = b2c, acc1 = b2c;

        const float* shbase = &s[SM_SH + p0];
        const float* wbase  = &s[SM_W2P + co * (Hdim * 8)];
#pragma unroll 8
        for (int ci = 0; ci < Hdim; ci++) {
            const float* shp = shbase + ci * SH_STR;
            float2 aA = *(const float2*)(shp);      // h[p0], h[p0+1]
            float2 aB = *(const float2*)(shp + 2);  // h[p0+2], h[p0+3]
            float2 aC = *(const float2*)(shp + 4);  // h[p0+4], h[p0+5]
            const float* wp = wbase + ci * 8;
            float4 w4 = *(const float4*)(wp);       // 16B-aligned (stride 8)
            float  w4k = wp[4];

            acc0 = fmaf(w4.x, aA.x, acc0);
            acc1 = fmaf(w4.x, aA.y, acc1);
            acc0 = fmaf(w4.y, aA.y, acc0);
            acc1 = fmaf(w4.y, aB.x, acc1);
            acc0 = fmaf(w4.z, aB.x, acc0);
            acc1 = fmaf(w4.z, aB.y, acc1);
            acc0 = fmaf(w4.w, aB.y, acc0);
            acc1 = fmaf(w4.w, aC.x, acc1);
            acc0 = fmaf(w4k,  aC.x, acc0);
            acc1 = fmaf(w4k,  aC.y, acc1);
        }

        const int row = (m * Ndim + co) * Ldim;
        float2 zv = *(const float2*)&z[row + base + p0];   // even p0 -> 8B aligned
        float zz[2] = {zv.x, zv.y};
        float ac[2] = {acc0, acc1};

#pragma unroll
        for (int j = 0; j < 2; j++) {
            float uu  = s[SM_SU + co * SU_STR + 4 + p0 + j];
            float val = alpha * zz[j] + beta * uu + gamma * ac[j];
            int x = base + p0 + j;
            // fused bdry: periodic ghost refresh, each out element written once
            if (x >= Gg && x < Ldim - Gg)            out[row + x] = val;
            if (x >= Ldim - 2 * Gg && x < Ldim - Gg) out[row + x - (Ldim - 2 * Gg)] = val;
            if (x >= Gg && x < 2 * Gg)               out[row + x + (Ldim - 2 * Gg)] = val;
        }
    }
}

extern "C" void kernel_launch(void* const* d_in, const int* in_sizes, int n_in,
                              void* d_out, int out_size) {
    const float* z0 = (const float*)d_in[0];
    const float* W1 = (const float*)d_in[1];
    const float* b1 = (const float*)d_in[2];
    const float* W2 = (const float*)d_in[3];
    const float* b2 = (const float*)d_in[4];
    float* out = (float*)d_out;

    float *A, *B, *C0, *C1;
    cudaGetSymbolAddress((void**)&A,  g_bufA);
    cudaGetSymbolAddress((void**)&B,  g_bufB);
    cudaGetSymbolAddress((void**)&C0, g_bufC0);
    cudaGetSymbolAddress((void**)&C1, g_bufC1);

    const size_t smem = SM_TOT * sizeof(float);
    cudaFuncSetAttribute(stage_kernel, cudaFuncAttributeMaxDynamicSharedMemorySize,
                         (int)smem);

    dim3 grid(TILES, Mdim);
    dim3 blk(NT);

    const float h = 1.0f / (float)NSTEPS;  // t1_t0 = 1 -> h = 0.05

    const float* Z = z0;
    float* cbuf[2] = {C0, C1};
    for (int st = 0; st < NSTEPS; st++) {
        float* zo = (st == NSTEPS - 1) ? out : cbuf[st & 1];
        // k1 = bdry(z + h f(z))
        stage_kernel<<<grid, blk, smem>>>(Z, Z, A, W1, b1, W2, b2,
                                          1.0f, 0.0f, h);
        // k2 = bdry(0.75 z + 0.25 k1 + 0.25 h f(k1))
        stage_kernel<<<grid, blk, smem>>>(Z, A, B, W1, b1, W2, b2,
                                          0.75f, 0.25f, 0.25f * h);
        // z' = bdry(z/3 + 2/3 k2 + 2h/3 f(k2))
        stage_kernel<<<grid, blk, smem>>>(Z, B, zo, W1, b1, W2, b2,
                                          1.0f / 3.0f, 2.0f / 3.0f, (2.0f / 3.0f) * h);
        Z = zo;
    }
}

// round 7
// speedup vs baseline: 2.8554x; 2.4639x over previous
#include <cuda_runtime.h>

// Problem constants
#define Mdim 32
#define Ndim 4
#define Ldim 2048
#define Hdim 64
#define Kdim 5
#define Gg   10
#define Pdim (Ldim - 2 * Gg)   // 2028: periodic interior ring
#define NSTEPS 20

// Fused kernel tiling
#define LT 256
#define NT 256
#define NTILES 8               // 8*256 = 2048 >= 2028 (last tile width 236)

// Fused smem layout (floats). Slot j of Z/KB <-> torus x = base - 12 + j.
#define ZS 280                  // input/k buffer stride (covers [-12, 268))
#define HS 284                  // h1 stride (284%32=28 -> co-spread banks; %4==0)
#define AW 276                  // phase A width: h1 slots [0, 276)
#define BW 272                  // phase B width: conv-out slots, x = base-8+oj
#define W2S 520                 // W2 co-stride (520%32=8 -> conflict-free)
#define F_W1 0                  // 64*4*5 = 1280
#define F_B1 1280               // 64
#define F_W2 1344               // 4*520 = 2080 (k padded to 8, pads unread)
#define F_B2 3424               // 4
#define F_Z  3428               // 4*280 = 1120
#define F_KB (F_Z + Ndim * ZS)  // 4548
#define F_H  (F_KB + Ndim * ZS) // 5668
#define F_TOT (F_H + Hdim * HS) // 23844 floats = 95376 B -> 2 CTAs/SM

// Stage-1 (raw) kernel smem layout (R1-proven shape)
#define S_SU_STR 264
#define S_SH_STR 264
#define S_W1 0
#define S_B1 (S_W1 + Hdim * Ndim * Kdim)
#define S_W2 (S_B1 + Hdim)
#define S_B2 (S_W2 + Ndim * Hdim * Kdim)
#define S_SU (S_B2 + Ndim)
#define S_SH (S_SU + Ndim * S_SU_STR)
#define S_TOT (S_SH + Hdim * S_SH_STR)   // 20580 floats

// Torus-state scratch (no cudaMalloc allowed)
__device__ float g_k1[Mdim * Ndim * Pdim];
__device__ float g_s0[Mdim * Ndim * Pdim];
__device__ float g_s1[Mdim * Ndim * Pdim];

__device__ __forceinline__ float my_tanh(float x) {
    float e = __expf(2.0f * x);
    return 1.0f - __fdividef(2.0f, e + 1.0f);
}

// ===================== Stage-1 kernel (raw domain, step 1 only) ==============
// k1 = bdry(z0 + h f(z0)) with raw zero-pad conv; writes TORUS layout.
__global__ void __launch_bounds__(NT)
stage1_raw_kernel(const float* __restrict__ z,
                  float* __restrict__ k1t,
                  const float* __restrict__ W1, const float* __restrict__ b1,
                  const float* __restrict__ W2, const float* __restrict__ b2,
                  float h)
{
    extern __shared__ float s[];
    const int tid  = threadIdx.x;
    const int m    = blockIdx.y;
    const int base = blockIdx.x * LT;

    for (int i = tid; i < Hdim * Ndim * Kdim; i += NT) s[S_W1 + i] = W1[i];
    for (int i = tid; i < Hdim; i += NT)               s[S_B1 + i] = b1[i];
    for (int i = tid; i < Ndim * Hdim * Kdim; i += NT) s[S_W2 + i] = W2[i];
    for (int i = tid; i < Ndim; i += NT)               s[S_B2 + i] = b2[i];

    for (int t = tid; t < Ndim * S_SU_STR; t += NT) {
        int ci = t / S_SU_STR;
        int j  = t - ci * S_SU_STR;
        int gx = base - 4 + j;
        float v = 0.0f;
        if (gx >= 0 && gx < Ldim) v = z[(m * Ndim + ci) * Ldim + gx];
        s[S_SU + ci * S_SU_STR + j] = v;
    }
    __syncthreads();

    {   // Phase A
        const int co   = tid >> 2;
        const int psub = tid & 3;
        float w1r[Ndim][Kdim];
#pragma unroll
        for (int ci = 0; ci < Ndim; ci++)
#pragma unroll
            for (int k = 0; k < Kdim; k++)
                w1r[ci][k] = s[S_W1 + (co * Ndim + ci) * Kdim + k];
        const float b1c = s[S_B1 + co];

        for (int pb = psub; pb < (LT + 4) / 4; pb += 4) {
            const int pp0 = pb * 4;
            float acc[4] = {b1c, b1c, b1c, b1c};
#pragma unroll
            for (int ci = 0; ci < Ndim; ci++) {
                const float* sup = &s[S_SU + ci * S_SU_STR + pp0];
                float4 va = *(const float4*)(sup);
                float4 vb = *(const float4*)(sup + 4);
                float x[8] = {va.x, va.y, va.z, va.w, vb.x, vb.y, vb.z, vb.w};
#pragma unroll
                for (int j = 0; j < 4; j++)
#pragma unroll
                    for (int k = 0; k < Kdim; k++)
                        acc[j] = fmaf(w1r[ci][k], x[j + k], acc[j]);
            }
#pragma unroll
            for (int j = 0; j < 4; j++) {
                int hx = base - 2 + pp0 + j;
                float v = (hx >= 0 && hx < Ldim) ? my_tanh(acc[j]) : 0.0f;
                s[S_SH + co * S_SH_STR + pp0 + j] = v;
            }
        }
    }
    __syncthreads();

    {   // Phase B: k1 = z + h * conv2(h1); torus write
        const int co = tid & 3;
        const int p0 = (tid >> 2) * 4;

        const float b2c = s[S_B2 + co];
        float acc[4] = {b2c, b2c, b2c, b2c};

#pragma unroll 8
        for (int ci = 0; ci < Hdim; ci++) {
            const float* shp = &s[S_SH + ci * S_SH_STR + p0];
            float4 va = *(const float4*)(shp);
            float4 vb = *(const float4*)(shp + 4);
            float x[8] = {va.x, va.y, va.z, va.w, vb.x, vb.y, vb.z, vb.w};
            const float* wp = &s[S_W2 + (co * Hdim + ci) * Kdim];
            float wk[Kdim];
#pragma unroll
            for (int k = 0; k < Kdim; k++) wk[k] = wp[k];
#pragma unroll
            for (int j = 0; j < 4; j++)
#pragma unroll
                for (int k = 0; k < Kdim; k++)
                    acc[j] = fmaf(wk[k], x[j + k], acc[j]);
        }

        const int row = (m * Ndim + co) * Ldim;
        float4 zv = *(const float4*)&z[row + base + p0];
        float zz[4] = {zv.x, zv.y, zv.z, zv.w};
        const int rowT = (m * Ndim + co) * Pdim;

#pragma unroll
        for (int j = 0; j < 4; j++) {
            float val = zz[j] + h * acc[j];
            int x = base + p0 + j;
            if (x >= Gg && x < Ldim - Gg) k1t[rowT + (x - Gg)] = val;
        }
    }
}

// ===================== Fused per-step kernel (torus domain) ==================
// Runs RK stages (skip1 ? {2,3} : {1,2,3}) for one time step on the ring.
__global__ void __launch_bounds__(NT)
fused_step_kernel(const float* __restrict__ zin,   // torus state (or raw z0 if firstRaw)
                  const float* __restrict__ k1in,  // torus k1 (used iff skip1)
                  float* __restrict__ zout,        // torus next state (iff !lastOut)
                  float* __restrict__ outF,        // raw final output (iff lastOut)
                  const float* __restrict__ W1, const float* __restrict__ b1,
                  const float* __restrict__ W2, const float* __restrict__ b2,
                  int firstRaw, int skip1, int lastOut)
{
    extern __shared__ float s[];
    const int tid  = threadIdx.x;
    const int m    = blockIdx.y;
    const int base = blockIdx.x * LT;
    const float h  = 1.0f / (float)NSTEPS;

    // ---- weights ----
    for (int i = tid; i < Hdim * Ndim * Kdim; i += NT) s[F_W1 + i] = W1[i];
    for (int i = tid; i < Hdim; i += NT)               s[F_B1 + i] = b1[i];
    for (int i = tid; i < Ndim * Hdim * Kdim; i += NT) {
        int co = i / (Hdim * Kdim);
        int r  = i - co * (Hdim * Kdim);
        int ci = r / Kdim, k = r - ci * Kdim;
        s[F_W2 + co * W2S + ci * 8 + k] = W2[i];       // pads k=5..7 never read
    }
    for (int i = tid; i < Ndim; i += NT)               s[F_B2 + i] = b2[i];

    // ---- z tile (torus wrap; firstRaw reads raw z0 interior at Gg+t) ----
    {
        const int zpitch = firstRaw ? Ldim : Pdim;
        const int zoff   = firstRaw ? Gg : 0;
        for (int j = tid; j < Ndim * ZS; j += NT) {
            int ci = j / ZS;
            int jj = j - ci * ZS;
            int t  = base - 12 + jj;
            if (t < 0) t += Pdim; else if (t >= Pdim) t -= Pdim;
            s[F_Z + ci * ZS + jj] = zin[(m * Ndim + ci) * zpitch + zoff + t];
        }
    }
    // ---- k1 tile from gmem when skipping stage 1 ----
    if (skip1) {
        for (int j = tid; j < Ndim * ZS; j += NT) {
            int ci = j / ZS;
            int jj = j - ci * ZS;
            int t  = base - 12 + jj;
            if (t < 0) t += Pdim; else if (t >= Pdim) t -= Pdim;
            s[F_KB + ci * ZS + jj] = k1in[(m * Ndim + ci) * Pdim + t];
        }
    }
    __syncthreads();

    // per-thread conv1 weights (co_a fixed across stages)
    const int co_a = tid >> 2;
    const int psub = tid & 3;
    float w1r[Ndim][Kdim];
#pragma unroll
    for (int ci = 0; ci < Ndim; ci++)
#pragma unroll
        for (int k = 0; k < Kdim; k++)
            w1r[ci][k] = s[F_W1 + (co_a * Ndim + ci) * Kdim + k];
    const float b1c = s[F_B1 + co_a];
    const float b2c = s[F_B2 + (tid & 3)];

    const float AL[3] = {1.0f, 0.75f, 1.0f / 3.0f};
    const float BE[3] = {0.0f, 0.25f, 2.0f / 3.0f};
    const float GA[3] = {h, 0.25f * h, (2.0f / 3.0f) * h};

    for (int st = skip1 ? 1 : 0; st < 3; st++) {
        const float* uin = &s[(st == 0) ? F_Z : F_KB];

        // ---- Phase A: h1[hj] = tanh(conv1(uin)), hj in [0, AW) ----
        {
            const float* urow0 = uin;   // stride ZS per channel
            for (int hq = psub; hq < AW / 4; hq += 4) {
                const int jh0 = hq * 4;
                float acc[4] = {b1c, b1c, b1c, b1c};
#pragma unroll
                for (int ci = 0; ci < Ndim; ci++) {
                    const float* up = urow0 + ci * ZS + jh0;
                    float4 va = *(const float4*)(up);
                    float4 vb = *(const float4*)(up + 4);
                    float x[8] = {va.x, va.y, va.z, va.w, vb.x, vb.y, vb.z, vb.w};
#pragma unroll
                    for (int j = 0; j < 4; j++)
#pragma unroll
                        for (int k = 0; k < Kdim; k++)
                            acc[j] = fmaf(w1r[ci][k], x[j + k], acc[j]);
                }
                float4 hv;
                hv.x = my_tanh(acc[0]);
                hv.y = my_tanh(acc[1]);
                hv.z = my_tanh(acc[2]);
                hv.w = my_tanh(acc[3]);
                *(float4*)&s[F_H + co_a * HS + jh0] = hv;
            }
        }
        __syncthreads();

        // ---- Phase B: out[oj] = AL*z + BE*uin + GA*(conv2(h1)+b2) ----
        {
            const int co = tid & 3;
            const float al = AL[st], be = BE[st], ga = GA[st];
            const float* wb   = &s[F_W2 + co * W2S];
            const float* zrow = &s[F_Z + co * ZS];
            const float* urow = uin + co * ZS;
            float* krow = &s[F_KB + co * ZS];

            for (int q = tid >> 2; q < BW / 4; q += 64) {
                const int oj = q * 4;
                float a0 = 0.f, a1 = 0.f, a2 = 0.f, a3 = 0.f;
                const float* hb = &s[F_H + oj];
#pragma unroll 4
                for (int ci = 0; ci < Hdim; ci++) {
                    const float* hp = hb + ci * HS;
                    float4 va = *(const float4*)(hp);
                    float4 vb = *(const float4*)(hp + 4);
                    const float* wp = wb + ci * 8;
                    float4 w4 = *(const float4*)(wp);
                    float  wk = wp[4];

                    a0 = fmaf(w4.x, va.x, a0);
                    a1 = fmaf(w4.x, va.y, a1);
                    a2 = fmaf(w4.x, va.z, a2);
                    a3 = fmaf(w4.x, va.w, a3);
                    a0 = fmaf(w4.y, va.y, a0);
                    a1 = fmaf(w4.y, va.z, a1);
                    a2 = fmaf(w4.y, va.w, a2);
                    a3 = fmaf(w4.y, vb.x, a3);
                    a0 = fmaf(w4.z, va.z, a0);
                    a1 = fmaf(w4.z, va.w, a1);
                    a2 = fmaf(w4.z, vb.x, a2);
                    a3 = fmaf(w4.z, vb.y, a3);
                    a0 = fmaf(w4.w, va.w, a0);
                    a1 = fmaf(w4.w, vb.x, a1);
                    a2 = fmaf(w4.w, vb.y, a2);
                    a3 = fmaf(w4.w, vb.z, a3);
                    a0 = fmaf(wk, vb.x, a0);
                    a1 = fmaf(wk, vb.y, a1);
                    a2 = fmaf(wk, vb.z, a2);
                    a3 = fmaf(wk, vb.w, a3);
                }
                float4 zq = *(const float4*)(zrow + oj + 4);
                float4 uq = *(const float4*)(urow + oj + 4);
                float4 kv;
                kv.x = al * zq.x + be * uq.x + ga * (a0 + b2c);
                kv.y = al * zq.y + be * uq.y + ga * (a1 + b2c);
                kv.z = al * zq.z + be * uq.z + ga * (a2 + b2c);
                kv.w = al * zq.w + be * uq.w + ga * (a3 + b2c);
                *(float4*)(krow + oj + 4) = kv;      // in-place k update (safe)
            }
        }
        __syncthreads();
    }

    // ---- epilogue: KB slot (p+12) holds z_new at torus t = base + p ----
    const int Wt = (Pdim - base < LT) ? (Pdim - base) : LT;
    if (!lastOut) {
#pragma unroll
        for (int ci = 0; ci < Ndim; ci++) {
            float* zo = &zout[(m * Ndim + ci) * Pdim + base];
            const float* kb = &s[F_KB + ci * ZS + 12];
            for (int p = tid; p < Wt; p += NT) zo[p] = kb[p];
        }
    } else {
#pragma unroll
        for (int ci = 0; ci < Ndim; ci++) {
            const int row = (m * Ndim + ci) * Ldim;
            const float* kb = &s[F_KB + ci * ZS + 12];
            for (int p = tid; p < Wt; p += NT) {
                float v = kb[p];
                int t = base + p;
                outF[row + Gg + t] = v;                          // interior
                if (t < Gg)        outF[row + Ldim - Gg + t] = v; // upper ghosts
                if (t >= Pdim - Gg) outF[row + t - (Pdim - Gg)] = v; // lower ghosts
            }
        }
    }
}

extern "C" void kernel_launch(void* const* d_in, const int* in_sizes, int n_in,
                              void* d_out, int out_size) {
    const float* z0 = (const float*)d_in[0];
    const float* W1 = (const float*)d_in[1];
    const float* b1 = (const float*)d_in[2];
    const float* W2 = (const float*)d_in[3];
    const float* b2 = (const float*)d_in[4];
    float* out = (float*)d_out;

    float *K1, *S0, *S1;
    cudaGetSymbolAddress((void**)&K1, g_k1);
    cudaGetSymbolAddress((void**)&S0, g_s0);
    cudaGetSymbolAddress((void**)&S1, g_s1);

    const size_t smem1 = S_TOT * sizeof(float);
    const size_t smemF = F_TOT * sizeof(float);
    cudaFuncSetAttribute(stage1_raw_kernel,
                         cudaFuncAttributeMaxDynamicSharedMemorySize, (int)smem1);
    cudaFuncSetAttribute(fused_step_kernel,
                         cudaFuncAttributeMaxDynamicSharedMemorySize, (int)smemF);

    dim3 grid(NTILES, Mdim);
    dim3 blk(NT);
    const float h = 1.0f / (float)NSTEPS;

    // Step 1, stage 1: raw domain (z0 ghosts are NOT periodic) -> torus k1
    stage1_raw_kernel<<<grid, blk, smem1>>>(z0, K1, W1, b1, W2, b2, h);
    // Step 1, stages 2-3: fused, z read raw-interior, k1 from gmem
    fused_step_kernel<<<grid, blk, smemF>>>(z0, K1, S0, out, W1, b1, W2, b2,
                                            /*firstRaw=*/1, /*skip1=*/1, /*last=*/0);
    // Steps 2..NSTEPS: fully fused on the torus
    float* cur = S0;
    float* nxt = S1;
    for (int st = 1; st < NSTEPS; st++) {
        int last = (st == NSTEPS - 1);
        fused_step_kernel<<<grid, blk, smemF>>>(cur, K1, nxt, out, W1, b1, W2, b2,
                                                0, 0, last);
        float* tmp = cur; cur = nxt; nxt = tmp;
    }
}